// round 5
// baseline (speedup 1.0000x reference)
#include <cuda_runtime.h>
#include <cstdint>

#define DIN   512
#define DOUT  4096
#define CAP   96          // max stored nonzeros per column

#define RB    64          // batch rows per GEMM CTA
#define WARPS 16
#define CPW   64          // columns per warp
#define XPITCH 66         // smem pitch for transposed x tile
#define OSP   9           // out-staging pitch

// ---------------- device scratch (static: allocation-free) ----------------
// g_list entries: {byte offset idx*XPITCH*4, fp32 bits of W*mask}, zero-padded
// to a multiple of 8 entries (exact: adding 0.0f is fp32-exact).
__device__ __align__(16) int2  g_list[DOUT * CAP];
__device__            int      g_nnz[DOUT];    // true nnz (clamped to CAP)
__device__            int      g_cnt[DOUT];    // ceil(min(nnz,64)/8) 8-elem blocks
__device__ __align__(16) float g_boost[DOUT];

// ---------------- kernel 1: compact sparse lists + boost ----------------
__global__ void k_prep(const float* __restrict__ W, const float* __restrict__ M,
                       const float* __restrict__ duty, const int* __restrict__ kptr) {
    int gt = blockIdx.x * blockDim.x + threadIdx.x;
    if (gt < DOUT) {
        float target = (float)(*kptr) / (float)DOUT;
        g_boost[gt] = expf(0.5f * (target - duty[gt]));
    }
    int j    = blockIdx.x * (blockDim.x >> 5) + (threadIdx.x >> 5);
    int lane = threadIdx.x & 31;
    if (j >= DOUT) return;
    const float* Wr = W + (size_t)j * DIN;
    const float* Mr = M + (size_t)j * DIN;
    int base = 0;
    for (int c = 0; c < DIN / 32; ++c) {
        int i = c * 32 + lane;
        float w = Wr[i] * Mr[i];                 // mask is exactly 0.0 or 1.0
        bool nz = (w != 0.0f);
        unsigned bal = __ballot_sync(0xffffffffu, nz);
        int pos = base + __popc(bal & ((1u << lane) - 1u));
        if (nz && pos < CAP)
            g_list[j * CAP + pos] = make_int2(i * XPITCH * 4, __float_as_int(w));
        base += __popc(bal);
    }
    int n      = (base < 64) ? base : 64;        // fast-path entry count
    int blocks = (n + 7) >> 3;                   // 8-elem blocks (0..8)
    int npad   = blocks * 8;
    if (n + lane < npad)                         // exact zero padding
        g_list[j * CAP + n + lane] = make_int2(0, 0);
    if (lane == 0) {
        g_cnt[j] = blocks;
        g_nnz[j] = (base < CAP) ? base : CAP;
    }
}

// ---------------- kernel 2: sparse gather GEMM (fp32 exact) ----------------
// Steady state has NO latency on the control path: block counts + bias staged
// in smem up front; list entries flow through a 4-slot smem ring with LDG
// issued 4 columns ahead of use. Inner loop: straight-line 8-element blocks
// (4x LDS.128 broadcast + 8x LDS.64 gather + 16 FFMA), trip count 1..8.
__global__ void __launch_bounds__(32 * WARPS, 1)
k_gemm(const float* __restrict__ x, const float* __restrict__ bias,
       float* __restrict__ yout) {
    extern __shared__ float sm[];
    float* xs   = sm;                              // [DIN][XPITCH]
    float* os   = xs + DIN * XPITCH;               // [WARPS][RB][OSP]
    int2*  ring = (int2*)(os + WARPS * RB * OSP);  // [WARPS][4][64] entries
    int*   scnt = (int*)(ring + WARPS * 4 * 64);   // [1024] block counts
    float* sbia = (float*)(scnt + WARPS * CPW);    // [1024] bias

    int tid  = threadIdx.x;
    int w    = tid >> 5;
    int lane = tid & 31;
    int rowbase = blockIdx.x * RB;
    int colbase = blockIdx.y * (WARPS * CPW);

    // stage x tile transposed + block counts + bias (all behind one barrier)
    const float4* x4 = (const float4*)(x + (size_t)rowbase * DIN);
    for (int t = tid; t < RB * (DIN / 4); t += blockDim.x) {
        int r  = t >> 7;
        int i4 = t & 127;
        float4 v = x4[(size_t)r * (DIN / 4) + i4];
        int ib = i4 * 4;
        xs[(ib + 0) * XPITCH + r] = v.x;
        xs[(ib + 1) * XPITCH + r] = v.y;
        xs[(ib + 2) * XPITCH + r] = v.z;
        xs[(ib + 3) * XPITCH + r] = v.w;
    }
    for (int t = tid; t < WARPS * CPW; t += blockDim.x) {
        scnt[t] = g_cnt[colbase + t];
        sbia[t] = __ldg(&bias[colbase + t]);
    }
    __syncthreads();

    float* osw   = os + w * (RB * OSP);
    int    jwarp = colbase + w * CPW;
    int    jloc0 = w * CPW;
    const char* xbase = (const char*)xs + lane * 8;
    int2*  rng   = ring + w * 4 * 64;

    // ---- prologue: stage cols 0,1; reg-hold cols 2,3 ----
    const int2* L;
    {
        L = &g_list[(size_t)jwarp * CAP];
        int2 a = __ldg(L + lane), b = __ldg(L + 32 + lane);
        rng[lane] = a; rng[32 + lane] = b;
        L = &g_list[(size_t)(jwarp + 1) * CAP];
        a = __ldg(L + lane); b = __ldg(L + 32 + lane);
        rng[64 + lane] = a; rng[96 + lane] = b;
    }
    L = &g_list[(size_t)(jwarp + 2) * CAP];
    int2 rA0 = __ldg(L + lane), rB0 = __ldg(L + 32 + lane);
    L = &g_list[(size_t)(jwarp + 3) * CAP];
    int2 rA1 = __ldg(L + lane), rB1 = __ldg(L + 32 + lane);
    __syncwarp();

    for (int ci = 0; ci < CPW; ++ci) {
        // stage col ci+2 (loaded 2 iters ago), prefetch col ci+4
        if (ci + 2 < CPW) {
            int2* sb = rng + ((ci + 2) & 3) * 64;
            sb[lane] = rA0; sb[32 + lane] = rB0;
            rA0 = rA1; rB0 = rB1;
            if (ci + 4 < CPW) {
                L = &g_list[(size_t)(jwarp + ci + 4) * CAP];
                rA1 = __ldg(L + lane); rB1 = __ldg(L + 32 + lane);
            }
        }

        int nb = scnt[jloc0 + ci];                 // broadcast LDS, no latency
        const int4* sb4 = (const int4*)(rng + (ci & 3) * 64);
        float acc0 = 0.f, acc1 = 0.f;
        #pragma unroll 1
        for (int t = 0; t < nb; ++t) {
            int4 q0 = sb4[t * 4 + 0];
            int4 q1 = sb4[t * 4 + 1];
            int4 q2 = sb4[t * 4 + 2];
            int4 q3 = sb4[t * 4 + 3];
            float2 a0 = *(const float2*)(xbase + q0.x);
            float2 a1 = *(const float2*)(xbase + q0.z);
            float2 a2 = *(const float2*)(xbase + q1.x);
            float2 a3 = *(const float2*)(xbase + q1.z);
            float2 a4 = *(const float2*)(xbase + q2.x);
            float2 a5 = *(const float2*)(xbase + q2.z);
            float2 a6 = *(const float2*)(xbase + q3.x);
            float2 a7 = *(const float2*)(xbase + q3.z);
            acc0 = fmaf(a0.x, __int_as_float(q0.y), acc0);
            acc1 = fmaf(a0.y, __int_as_float(q0.y), acc1);
            acc0 = fmaf(a1.x, __int_as_float(q0.w), acc0);
            acc1 = fmaf(a1.y, __int_as_float(q0.w), acc1);
            acc0 = fmaf(a2.x, __int_as_float(q1.y), acc0);
            acc1 = fmaf(a2.y, __int_as_float(q1.y), acc1);
            acc0 = fmaf(a3.x, __int_as_float(q1.w), acc0);
            acc1 = fmaf(a3.y, __int_as_float(q1.w), acc1);
            acc0 = fmaf(a4.x, __int_as_float(q2.y), acc0);
            acc1 = fmaf(a4.y, __int_as_float(q2.y), acc1);
            acc0 = fmaf(a5.x, __int_as_float(q2.w), acc0);
            acc1 = fmaf(a5.y, __int_as_float(q2.w), acc1);
            acc0 = fmaf(a6.x, __int_as_float(q3.y), acc0);
            acc1 = fmaf(a6.y, __int_as_float(q3.y), acc1);
            acc0 = fmaf(a7.x, __int_as_float(q3.w), acc0);
            acc1 = fmaf(a7.y, __int_as_float(q3.w), acc1);
        }
        if (nb == 8) {                              // ~never: nnz>64 fallback
            int j = jwarp + ci;
            int nn = __ldg(&g_nnz[j]);
            for (int e = 64; e < nn; ++e) {
                int2 pe = __ldg(&g_list[(size_t)j * CAP + e]);
                float2 xv = *(const float2*)(xbase + pe.x);
                acc0 = fmaf(xv.x, __int_as_float(pe.y), acc0);
                acc1 = fmaf(xv.y, __int_as_float(pe.y), acc1);
            }
        }
        float bj = sbia[jloc0 + ci];
        int cc = ci & 7;
        osw[(2 * lane)     * OSP + cc] = acc0 + bj;
        osw[(2 * lane + 1) * OSP + cc] = acc1 + bj;

        if (cc == 7) {
            __syncwarp();
            int j0 = jwarp + (ci & ~7);
            #pragma unroll
            for (int q = 0; q < 4; ++q) {
                int chunk = q * 32 + lane;
                int row   = chunk >> 1;
                int c0    = (chunk & 1) * 4;
                float4 v;
                v.x = osw[row * OSP + c0 + 0];
                v.y = osw[row * OSP + c0 + 1];
                v.z = osw[row * OSP + c0 + 2];
                v.w = osw[row * OSP + c0 + 3];
                *(float4*)&yout[(size_t)(rowbase + row) * DOUT + j0 + c0] = v;
            }
        }
        __syncwarp();   // ring-slot handoff
    }
}

// ---------------- kernel 3: per-row radix select + masked rewrite ----------------
__global__ void __launch_bounds__(256)
k_select(float* __restrict__ y, const int* __restrict__ kptr) {
    __shared__ float    ys[DOUT];
    __shared__ unsigned ks[DOUT];
    __shared__ unsigned hist[256];
    __shared__ unsigned s_prefix;
    __shared__ int      s_kk;

    int tid = threadIdx.x;
    size_t rowoff = (size_t)blockIdx.x * DOUT;
    const float4* y4 = (const float4*)(y + rowoff);
    const float4* b4 = (const float4*)g_boost;

    for (int t = tid; t < DOUT / 4; t += blockDim.x) {
        float4 v  = y4[t];
        float4 bo = b4[t];
        float bv[4] = { v.x * bo.x, v.y * bo.y, v.z * bo.z, v.w * bo.w };
        float vv[4] = { v.x, v.y, v.z, v.w };
        #pragma unroll
        for (int q = 0; q < 4; ++q) {
            ys[t * 4 + q] = vv[q];
            unsigned u = __float_as_uint(bv[q]);
            ks[t * 4 + q] = (u & 0x80000000u) ? ~u : (u | 0x80000000u);
        }
    }
    if (tid == 0) { s_prefix = 0u; s_kk = *kptr; }
    __syncthreads();

    for (int pass = 0; pass < 4; ++pass) {
        int shift = 24 - 8 * pass;
        unsigned prefix = s_prefix;
        int kk = s_kk;
        if (tid < 256) hist[tid] = 0u;
        __syncthreads();
        unsigned hi_mask = (pass == 0) ? 0u : (0xFFFFFFFFu << (shift + 8));
        for (int t = tid; t < DOUT; t += blockDim.x) {
            unsigned key = ks[t];
            bool act = ((key & hi_mask) == prefix);
            unsigned bal = __ballot_sync(0xffffffffu, act);
            if (act) {
                int bin = (key >> shift) & 255;
                unsigned mm = __match_any_sync(bal, bin);
                int leader = __ffs(mm) - 1;
                if ((tid & 31) == leader) atomicAdd(&hist[bin], __popc(mm));
            }
        }
        __syncthreads();
        if (tid == 0) {
            int acc = 0, b = 255;
            for (; b >= 0; --b) {
                int nb = acc + (int)hist[b];
                if (nb >= kk) break;
                acc = nb;
            }
            s_prefix = prefix | ((unsigned)b << shift);
            s_kk = kk - acc;
        }
        __syncthreads();
    }

    unsigned thr = s_prefix;
    float4* yo4 = (float4*)(y + rowoff);
    for (int t = tid; t < DOUT / 4; t += blockDim.x) {
        float4 v;
        v.x = (ks[t * 4 + 0] >= thr) ? ys[t * 4 + 0] : 0.f;
        v.y = (ks[t * 4 + 1] >= thr) ? ys[t * 4 + 1] : 0.f;
        v.z = (ks[t * 4 + 2] >= thr) ? ys[t * 4 + 2] : 0.f;
        v.w = (ks[t * 4 + 3] >= thr) ? ys[t * 4 + 3] : 0.f;
        yo4[t] = v;
    }
}

// ---------------- launch ----------------
extern "C" void kernel_launch(void* const* d_in, const int* in_sizes, int n_in,
                              void* d_out, int out_size) {
    const float* x    = (const float*)d_in[0];
    const float* W    = (const float*)d_in[1];
    const float* b    = (const float*)d_in[2];
    const float* m    = (const float*)d_in[3];
    const float* duty = (const float*)d_in[4];
    const int*   k    = (const int*)d_in[5];
    float* out = (float*)d_out;

    int B = in_sizes[0] / DIN;   // 16384

    k_prep<<<DOUT / 8, 256>>>(W, m, duty, k);

    const int smem_bytes = (DIN * XPITCH + WARPS * RB * OSP) * (int)sizeof(float)
                         + WARPS * 4 * 64 * (int)sizeof(int2)       // ring 32KB
                         + WARPS * CPW * (int)(sizeof(int) + sizeof(float)); // cnt+bias 8KB
    cudaFuncSetAttribute(k_gemm, cudaFuncAttributeMaxDynamicSharedMemorySize, smem_bytes);
    dim3 grid(B / RB, DOUT / (WARPS * CPW));   // (256, 4)
    k_gemm<<<grid, 32 * WARPS, smem_bytes>>>(x, b, out);

    k_select<<<B, 256>>>(out, k);
}